// round 2
// baseline (speedup 1.0000x reference)
#include <cuda_runtime.h>

// ---------------------------------------------------------------------------
// SparseUNet on dense 2x1024x1024 grid with occupancy masks.
// All intermediates are dense-exact (zeros off-mask), so dense kernels +
// output masking reproduce MinkowskiEngine semantics exactly.
// ---------------------------------------------------------------------------

#define NB 2

// ---- scratch buffers (device globals; no allocations allowed) -------------
__device__ float g_xm[NB * 1024 * 1024];            // masked input, 1ch
__device__ float g_c1[NB * 1024 * 1024 * 16];
__device__ float g_p1[NB * 512 * 512 * 16];
__device__ float g_p2[NB * 256 * 256 * 32];
__device__ float g_c3[NB * 256 * 256 * 64];
__device__ float g_p3[NB * 128 * 128 * 64];
__device__ float g_c4[NB * 128 * 128 * 128];
__device__ float g_p4[NB * 64 * 64 * 128];
__device__ float g_br[NB * 64 * 64 * 256];
__device__ float g_u4[NB * 128 * 128 * 128];
__device__ float g_r4[NB * 128 * 128 * 128];
__device__ float g_u3[NB * 256 * 256 * 64];
__device__ float g_r3[NB * 256 * 256 * 64];
__device__ float g_u2[NB * 512 * 512 * 32];
__device__ float g_r2[NB * 512 * 512 * 32];
__device__ float g_u1[NB * 1024 * 1024 * 16];
__device__ float g_r1[NB * 1024 * 1024 * 16];

__device__ unsigned char g_m0[NB * 1024 * 1024];
__device__ unsigned char g_m1[NB * 512 * 512];
__device__ unsigned char g_m2[NB * 256 * 256];
__device__ unsigned char g_m3[NB * 128 * 128];
__device__ unsigned char g_m4[NB * 64 * 64];
__device__ unsigned char g_mc4[NB * 128 * 128];
__device__ unsigned char g_mc3[NB * 256 * 256];
__device__ unsigned char g_mc2[NB * 512 * 512];
__device__ unsigned char g_mc1[NB * 1024 * 1024];

// ---------------------------------------------------------------------------
// Kernels
// ---------------------------------------------------------------------------

__global__ void k_init(const float* __restrict__ x, const int* __restrict__ m,
                       float* __restrict__ xm, unsigned char* __restrict__ m0, int n) {
    int i = blockIdx.x * blockDim.x + threadIdx.x;
    if (i >= n) return;
    int v = (m[i] != 0);
    m0[i] = (unsigned char)v;
    xm[i] = v ? x[i] : 0.0f;
}

// generic 3x3 SAME conv over (optionally) concatenated inputs A(Ca ch) ++ B(Cb ch)
// out[b,y,x,co] masked by msk; writes exact zeros off-mask.
__global__ void k_conv3(const float* __restrict__ A, const float* __restrict__ Bp,
                        int Ca, int Cb,
                        const float* __restrict__ w,          // [3,3,Ci,Co]
                        const unsigned char* __restrict__ msk,
                        float* __restrict__ out,
                        int B, int H, int W, int Co) {
    long long n = (long long)B * H * W * Co;
    long long i = (long long)blockIdx.x * blockDim.x + threadIdx.x;
    if (i >= n) return;
    int co = (int)(i % Co);
    long long t = i / Co;
    int x = (int)(t % W); t /= W;
    int y = (int)(t % H);
    int b = (int)(t / H);

    if (!msk[(b * H + y) * W + x]) { out[i] = 0.0f; return; }

    const int Ci = Ca + Cb;
    float acc = 0.0f;
#pragma unroll
    for (int ky = 0; ky < 3; ky++) {
        int yy = y + ky - 1;
        if ((unsigned)yy >= (unsigned)H) continue;
#pragma unroll
        for (int kx = 0; kx < 3; kx++) {
            int xx = x + kx - 1;
            if ((unsigned)xx >= (unsigned)W) continue;
            long long base = ((long long)(b * H + yy) * W + xx);
            const float* wp = w + ((long long)(ky * 3 + kx) * Ci) * Co + co;
            const float* ap = A + base * Ca;
            if ((Ca & 3) == 0) {
                for (int ci = 0; ci < Ca; ci += 4) {
                    float4 v = *reinterpret_cast<const float4*>(ap + ci);
                    acc = fmaf(v.x, wp[(ci + 0) * Co], acc);
                    acc = fmaf(v.y, wp[(ci + 1) * Co], acc);
                    acc = fmaf(v.z, wp[(ci + 2) * Co], acc);
                    acc = fmaf(v.w, wp[(ci + 3) * Co], acc);
                }
            } else {
                for (int ci = 0; ci < Ca; ci++)
                    acc = fmaf(ap[ci], wp[ci * Co], acc);
            }
            if (Cb > 0) {
                const float* bp = Bp + base * Cb;
                const float* wq = wp + (long long)Ca * Co;
                for (int ci = 0; ci < Cb; ci += 4) {
                    float4 v = *reinterpret_cast<const float4*>(bp + ci);
                    acc = fmaf(v.x, wq[(ci + 0) * Co], acc);
                    acc = fmaf(v.y, wq[(ci + 1) * Co], acc);
                    acc = fmaf(v.z, wq[(ci + 2) * Co], acc);
                    acc = fmaf(v.w, wq[(ci + 3) * Co], acc);
                }
            }
        }
    }
    out[i] = acc;
}

// 2x2 stride-2 occupancy pool of the mask
__global__ void k_maskpool(const unsigned char* __restrict__ mi, unsigned char* __restrict__ mo,
                           int B, int Ho, int Wo) {
    int i = blockIdx.x * blockDim.x + threadIdx.x;
    int n = B * Ho * Wo;
    if (i >= n) return;
    int xo = i % Wo; int t = i / Wo;
    int yo = t % Ho; int b = t / Ho;
    int Wi = 2 * Wo;
    const unsigned char* p = mi + ((b * 2 * Ho + 2 * yo) * Wi + 2 * xo);
    mo[i] = (p[0] | p[1] | p[Wi] | p[Wi + 1]) ? 1 : 0;
}

// 2x2 stride-2 max pool over occupied sites (0 where no site occupied)
__global__ void k_pool(const float* __restrict__ in, const unsigned char* __restrict__ mi,
                       float* __restrict__ out, int B, int Ho, int Wo, int C) {
    long long n = (long long)B * Ho * Wo * C;
    long long i = (long long)blockIdx.x * blockDim.x + threadIdx.x;
    if (i >= n) return;
    int c = (int)(i % C); long long t = i / C;
    int xo = (int)(t % Wo); t /= Wo;
    int yo = (int)(t % Ho);
    int b = (int)(t / Ho);
    int Wi = Wo * 2, Hi = Ho * 2;
    long long r0 = ((long long)(b * Hi + 2 * yo) * Wi + 2 * xo);
    const unsigned char* mp = mi + r0;
    float best = -3.4e38f; int any = 0;
    if (mp[0])      { best = fmaxf(best, in[(r0) * C + c]);          any = 1; }
    if (mp[1])      { best = fmaxf(best, in[(r0 + 1) * C + c]);      any = 1; }
    if (mp[Wi])     { best = fmaxf(best, in[(r0 + Wi) * C + c]);     any = 1; }
    if (mp[Wi + 1]) { best = fmaxf(best, in[(r0 + Wi + 1) * C + c]); any = 1; }
    out[i] = any ? best : 0.0f;
}

// mc[b,y,x] = mfine[b,y,x] | mcoarse[b,y/2,x/2]   (mu = 2x upsample of coarse)
__global__ void k_mc(const unsigned char* __restrict__ mcoarse,
                     const unsigned char* __restrict__ mfine,
                     unsigned char* __restrict__ mc, int B, int H, int W) {
    int i = blockIdx.x * blockDim.x + threadIdx.x;
    int n = B * H * W;
    if (i >= n) return;
    int x = i % W; int t = i / W;
    int y = t % H; int b = t / H;
    unsigned char v = mfine[i] | mcoarse[(b * (H / 2) + (y >> 1)) * (W / 2) + (x >> 1)];
    mc[i] = v ? 1 : 0;
}

// kernel-2 stride-2 transpose conv: out[b,2i+di,2j+dj,co] = sum_ci w[di,dj,ci,co]*in[b,i,j,ci]
// Input is exactly zero off-mask, so output is exactly zero at non-generated sites.
__global__ void k_tconv(const float* __restrict__ in, const float* __restrict__ w,
                        float* __restrict__ out, int B, int Hi, int Wi, int Ci, int Co) {
    long long n = (long long)B * Hi * Wi * 4 * Co;
    long long i = (long long)blockIdx.x * blockDim.x + threadIdx.x;
    if (i >= n) return;
    int co = (int)(i % Co); long long t = i / Co;
    int Wo = Wi * 2, Ho = Hi * 2;
    int x = (int)(t % Wo); t /= Wo;
    int y = (int)(t % Ho);
    int b = (int)(t / Ho);
    const float* wp = w + ((long long)((y & 1) * 2 + (x & 1)) * Ci) * Co + co;
    const float* ip = in + ((long long)(b * Hi + (y >> 1)) * Wi + (x >> 1)) * Ci;
    float acc = 0.0f;
    for (int ci = 0; ci < Ci; ci += 4) {
        float4 v = *reinterpret_cast<const float4*>(ip + ci);
        acc = fmaf(v.x, wp[(ci + 0) * Co], acc);
        acc = fmaf(v.y, wp[(ci + 1) * Co], acc);
        acc = fmaf(v.z, wp[(ci + 2) * Co], acc);
        acc = fmaf(v.w, wp[(ci + 3) * Co], acc);
    }
    out[i] = acc;
}

// final 1x1 conv 16 -> 3, masked
__global__ void k_out1x1(const float* __restrict__ in, const float* __restrict__ w,
                         const unsigned char* __restrict__ msk, float* __restrict__ out, int n) {
    int i = blockIdx.x * blockDim.x + threadIdx.x;
    if (i >= n) return;
    if (!msk[i]) {
        out[(long long)i * 3 + 0] = 0.0f;
        out[(long long)i * 3 + 1] = 0.0f;
        out[(long long)i * 3 + 2] = 0.0f;
        return;
    }
    const float* ip = in + (long long)i * 16;
    float a0 = 0.0f, a1 = 0.0f, a2 = 0.0f;
#pragma unroll
    for (int c = 0; c < 16; c++) {
        float v = ip[c];
        a0 = fmaf(v, w[c * 3 + 0], a0);
        a1 = fmaf(v, w[c * 3 + 1], a1);
        a2 = fmaf(v, w[c * 3 + 2], a2);
    }
    out[(long long)i * 3 + 0] = a0;
    out[(long long)i * 3 + 1] = a1;
    out[(long long)i * 3 + 2] = a2;
}

// ---------------------------------------------------------------------------
// Host launcher
// ---------------------------------------------------------------------------

static inline unsigned grid_for(long long n) { return (unsigned)((n + 255) / 256); }

extern "C" void kernel_launch(void* const* d_in, const int* in_sizes, int n_in,
                              void* d_out, int out_size) {
    (void)in_sizes; (void)n_in; (void)out_size;

    const float* x       = (const float*)d_in[0];
    const int*   mask    = (const int*)d_in[1];
    const float* w_ds1   = (const float*)d_in[2];
    const float* w_ds2   = (const float*)d_in[3];
    const float* w_ds3   = (const float*)d_in[4];
    const float* w_ds4   = (const float*)d_in[5];
    const float* w_brdg  = (const float*)d_in[6];
    const float* wt4     = (const float*)d_in[7];
    const float* w_us4   = (const float*)d_in[8];
    const float* wt3     = (const float*)d_in[9];
    const float* w_us3   = (const float*)d_in[10];
    const float* wt2     = (const float*)d_in[11];
    const float* w_us2   = (const float*)d_in[12];
    const float* wt1     = (const float*)d_in[13];
    const float* w_us1   = (const float*)d_in[14];
    const float* w_out   = (const float*)d_in[15];

    float* out_final = (float*)d_out;                       // [2,1024,1024,3]
    float* c2        = (float*)d_out + (long long)NB * 1024 * 1024 * 3;  // [2,512,512,32]

    float *xm, *c1, *p1, *p2, *c3, *p3, *c4, *p4, *br, *u4, *r4, *u3, *r3, *u2, *r2, *u1, *r1;
    unsigned char *m0, *m1, *m2, *m3, *m4, *mc4, *mc3, *mc2, *mc1;
    cudaGetSymbolAddress((void**)&xm, g_xm);
    cudaGetSymbolAddress((void**)&c1, g_c1);
    cudaGetSymbolAddress((void**)&p1, g_p1);
    cudaGetSymbolAddress((void**)&p2, g_p2);
    cudaGetSymbolAddress((void**)&c3, g_c3);
    cudaGetSymbolAddress((void**)&p3, g_p3);
    cudaGetSymbolAddress((void**)&c4, g_c4);
    cudaGetSymbolAddress((void**)&p4, g_p4);
    cudaGetSymbolAddress((void**)&br, g_br);
    cudaGetSymbolAddress((void**)&u4, g_u4);
    cudaGetSymbolAddress((void**)&r4, g_r4);
    cudaGetSymbolAddress((void**)&u3, g_u3);
    cudaGetSymbolAddress((void**)&r3, g_r3);
    cudaGetSymbolAddress((void**)&u2, g_u2);
    cudaGetSymbolAddress((void**)&r2, g_r2);
    cudaGetSymbolAddress((void**)&u1, g_u1);
    cudaGetSymbolAddress((void**)&r1, g_r1);
    cudaGetSymbolAddress((void**)&m0, g_m0);
    cudaGetSymbolAddress((void**)&m1, g_m1);
    cudaGetSymbolAddress((void**)&m2, g_m2);
    cudaGetSymbolAddress((void**)&m3, g_m3);
    cudaGetSymbolAddress((void**)&m4, g_m4);
    cudaGetSymbolAddress((void**)&mc4, g_mc4);
    cudaGetSymbolAddress((void**)&mc3, g_mc3);
    cudaGetSymbolAddress((void**)&mc2, g_mc2);
    cudaGetSymbolAddress((void**)&mc1, g_mc1);

    const int TB = 256;
    long long n;

    // init mask + masked input
    n = (long long)NB * 1024 * 1024;
    k_init<<<grid_for(n), TB>>>(x, mask, xm, m0, (int)n);

    // --- encoder ---
    n = (long long)NB * 1024 * 1024 * 16;
    k_conv3<<<grid_for(n), TB>>>(xm, nullptr, 1, 0, w_ds1, m0, c1, NB, 1024, 1024, 16);

    n = (long long)NB * 512 * 512;
    k_maskpool<<<grid_for(n), TB>>>(m0, m1, NB, 512, 512);
    n = (long long)NB * 512 * 512 * 16;
    k_pool<<<grid_for(n), TB>>>(c1, m0, p1, NB, 512, 512, 16);

    n = (long long)NB * 512 * 512 * 32;
    k_conv3<<<grid_for(n), TB>>>(p1, nullptr, 16, 0, w_ds2, m1, c2, NB, 512, 512, 32);

    n = (long long)NB * 256 * 256;
    k_maskpool<<<grid_for(n), TB>>>(m1, m2, NB, 256, 256);
    n = (long long)NB * 256 * 256 * 32;
    k_pool<<<grid_for(n), TB>>>(c2, m1, p2, NB, 256, 256, 32);

    n = (long long)NB * 256 * 256 * 64;
    k_conv3<<<grid_for(n), TB>>>(p2, nullptr, 32, 0, w_ds3, m2, c3, NB, 256, 256, 64);

    n = (long long)NB * 128 * 128;
    k_maskpool<<<grid_for(n), TB>>>(m2, m3, NB, 128, 128);
    n = (long long)NB * 128 * 128 * 64;
    k_pool<<<grid_for(n), TB>>>(c3, m2, p3, NB, 128, 128, 64);

    n = (long long)NB * 128 * 128 * 128;
    k_conv3<<<grid_for(n), TB>>>(p3, nullptr, 64, 0, w_ds4, m3, c4, NB, 128, 128, 128);

    n = (long long)NB * 64 * 64;
    k_maskpool<<<grid_for(n), TB>>>(m3, m4, NB, 64, 64);
    n = (long long)NB * 64 * 64 * 128;
    k_pool<<<grid_for(n), TB>>>(c4, m3, p4, NB, 64, 64, 128);

    // --- bridge ---
    n = (long long)NB * 64 * 64 * 256;
    k_conv3<<<grid_for(n), TB>>>(p4, nullptr, 128, 0, w_brdg, m4, br, NB, 64, 64, 256);

    // --- decoder level 4 ---
    n = (long long)NB * 128 * 128 * 128;
    k_tconv<<<grid_for(n), TB>>>(br, wt4, u4, NB, 64, 64, 256, 128);
    n = (long long)NB * 128 * 128;
    k_mc<<<grid_for(n), TB>>>(m4, m3, mc4, NB, 128, 128);
    n = (long long)NB * 128 * 128 * 128;
    k_conv3<<<grid_for(n), TB>>>(u4, c4, 128, 128, w_us4, mc4, r4, NB, 128, 128, 128);

    // --- decoder level 3 ---
    n = (long long)NB * 256 * 256 * 64;
    k_tconv<<<grid_for(n), TB>>>(r4, wt3, u3, NB, 128, 128, 128, 64);
    n = (long long)NB * 256 * 256;
    k_mc<<<grid_for(n), TB>>>(mc4, m2, mc3, NB, 256, 256);
    n = (long long)NB * 256 * 256 * 64;
    k_conv3<<<grid_for(n), TB>>>(u3, c3, 64, 64, w_us3, mc3, r3, NB, 256, 256, 64);

    // --- decoder level 2 ---
    n = (long long)NB * 512 * 512 * 32;
    k_tconv<<<grid_for(n), TB>>>(r3, wt2, u2, NB, 256, 256, 64, 32);
    n = (long long)NB * 512 * 512;
    k_mc<<<grid_for(n), TB>>>(mc3, m1, mc2, NB, 512, 512);
    n = (long long)NB * 512 * 512 * 32;
    k_conv3<<<grid_for(n), TB>>>(u2, c2, 32, 32, w_us2, mc2, r2, NB, 512, 512, 32);

    // --- decoder level 1 ---
    n = (long long)NB * 1024 * 1024 * 16;
    k_tconv<<<grid_for(n), TB>>>(r2, wt1, u1, NB, 512, 512, 32, 16);
    n = (long long)NB * 1024 * 1024;
    k_mc<<<grid_for(n), TB>>>(mc2, m0, mc1, NB, 1024, 1024);
    n = (long long)NB * 1024 * 1024 * 16;
    k_conv3<<<grid_for(n), TB>>>(u1, c1, 16, 16, w_us1, mc1, r1, NB, 1024, 1024, 16);

    // --- output head ---
    n = (long long)NB * 1024 * 1024;
    k_out1x1<<<grid_for(n), TB>>>(r1, w_out, mc1, out_final, (int)n);
}

// round 5
// speedup vs baseline: 2.6664x; 2.6664x over previous
#include <cuda_runtime.h>

// ---------------------------------------------------------------------------
// SparseUNet, CHW layout everywhere. Dense kernels + exact-zero masking
// reproduce MinkowskiEngine sparse semantics bit-for-bit (fp32 math).
// Conv: register-tiled direct conv, 4 pixels x 8 co per thread, warp spans
// contiguous x -> all input LDGs 1 wavefront; weights uniform float4.
// ---------------------------------------------------------------------------

#define NB 2
#define CONV_COT 8
#define T_COT 4

// ---- scratch (device globals; allocations forbidden) ----------------------
__device__ float g_xm[NB * 1024 * 1024];                 // 1ch, CHW==NHWC
__device__ float g_c1[NB * 16 * 1024 * 1024];
__device__ float g_p1[NB * 16 * 512 * 512];
__device__ float g_c2[NB * 32 * 512 * 512];              // CHW copy of c2
__device__ float g_p2[NB * 32 * 256 * 256];
__device__ float g_c3[NB * 64 * 256 * 256];
__device__ float g_p3[NB * 64 * 128 * 128];
__device__ float g_c4[NB * 128 * 128 * 128];
__device__ float g_p4[NB * 128 * 64 * 64];
__device__ float g_br[NB * 256 * 64 * 64];
__device__ float g_u4[NB * 128 * 128 * 128];
__device__ float g_r4[NB * 128 * 128 * 128];
__device__ float g_u3[NB * 64 * 256 * 256];
__device__ float g_r3[NB * 64 * 256 * 256];
__device__ float g_u2[NB * 32 * 512 * 512];
__device__ float g_r2[NB * 32 * 512 * 512];
__device__ float g_u1[NB * 16 * 1024 * 1024];
__device__ float g_r1[NB * 16 * 1024 * 1024];

__device__ unsigned char g_m0[NB * 1024 * 1024];
__device__ unsigned char g_m1[NB * 512 * 512];
__device__ unsigned char g_m2[NB * 256 * 256];
__device__ unsigned char g_m3[NB * 128 * 128];
__device__ unsigned char g_m4[NB * 64 * 64];
__device__ unsigned char g_mc4[NB * 128 * 128];
__device__ unsigned char g_mc3[NB * 256 * 256];
__device__ unsigned char g_mc2[NB * 512 * 512];
__device__ unsigned char g_mc1[NB * 1024 * 1024];

// ---------------------------------------------------------------------------
__global__ void k_init(const float* __restrict__ x, const int* __restrict__ m,
                       float* __restrict__ xm, unsigned char* __restrict__ m0, int n) {
    int i = blockIdx.x * blockDim.x + threadIdx.x;
    if (i >= n) return;
    int v = (m[i] != 0);
    m0[i] = (unsigned char)v;
    xm[i] = v ? x[i] : 0.0f;
}

// ---------------------------------------------------------------------------
// 3x3 SAME conv, CHW in/out, concat inputs A(Ca)++B(Cb), weights [3,3,Ci,Co].
// Each thread: 4 pixels (stride 256 in flat pixel index) x CONV_COT co.
// ---------------------------------------------------------------------------
__global__ void conv3_chw(const float* __restrict__ A, const float* __restrict__ Bp,
                          int Ca, int Cb,
                          const float* __restrict__ w,
                          const unsigned char* __restrict__ msk,
                          float* __restrict__ out,
                          int H, int W, int Co) {
    const int HW = H * W;
    const int b = blockIdx.z;
    const int cobase = blockIdx.y * CONV_COT;
    const int tid = threadIdx.x;
    const int Ci = Ca + Cb;

    int pi[4];
    int offr[4][3];
    unsigned vmask[4];
    bool pv[4];
#pragma unroll
    for (int p = 0; p < 4; p++) {
        pi[p] = blockIdx.x * 1024 + p * 256 + tid;
        pv[p] = pi[p] < HW;
        int pp = pv[p] ? pi[p] : 0;
        int y = pp / W, x = pp % W;
        unsigned mm = 0;
#pragma unroll
        for (int ky = 0; ky < 3; ky++) {
            int yy = y + ky - 1;
            bool rok = (unsigned)yy < (unsigned)H;
            offr[p][ky] = yy * W + x - 1;
#pragma unroll
            for (int kx = 0; kx < 3; kx++) {
                int xx = x + kx - 1;
                if (rok && (unsigned)xx < (unsigned)W && pv[p])
                    mm |= 1u << (ky * 3 + kx);
            }
        }
        vmask[p] = mm;
    }

    float acc[4][CONV_COT];
#pragma unroll
    for (int p = 0; p < 4; p++)
#pragma unroll
        for (int j = 0; j < CONV_COT; j++) acc[p][j] = 0.0f;

    const float* srcs[2] = {A, Bp};
    const int ccs[2] = {Ca, Cb};
    const int coffs[2] = {0, Ca};
    const long long tapstride = (long long)Ci * Co;

    for (int s = 0; s < 2; s++) {
        const float* src = srcs[s];
        const int Cc = ccs[s];
        if (Cc == 0) continue;
        const int coff = coffs[s];
        for (int ci = 0; ci < Cc; ci++) {
            const float* ip = src + (long long)(b * Cc + ci) * HW;
            const float* wci = w + (long long)(coff + ci) * Co + cobase;
#pragma unroll
            for (int ky = 0; ky < 3; ky++) {
#pragma unroll
                for (int kx = 0; kx < 3; kx++) {
                    const float* wp = wci + (long long)(ky * 3 + kx) * tapstride;
                    float4 w0 = *reinterpret_cast<const float4*>(wp);
                    float4 w1 = *reinterpret_cast<const float4*>(wp + 4);
#pragma unroll
                    for (int p = 0; p < 4; p++) {
                        float v = 0.0f;
                        if (vmask[p] & (1u << (ky * 3 + kx)))
                            v = __ldg(ip + offr[p][ky] + kx);
                        acc[p][0] = fmaf(v, w0.x, acc[p][0]);
                        acc[p][1] = fmaf(v, w0.y, acc[p][1]);
                        acc[p][2] = fmaf(v, w0.z, acc[p][2]);
                        acc[p][3] = fmaf(v, w0.w, acc[p][3]);
                        acc[p][4] = fmaf(v, w1.x, acc[p][4]);
                        acc[p][5] = fmaf(v, w1.y, acc[p][5]);
                        acc[p][6] = fmaf(v, w1.z, acc[p][6]);
                        acc[p][7] = fmaf(v, w1.w, acc[p][7]);
                    }
                }
            }
        }
    }

#pragma unroll
    for (int p = 0; p < 4; p++) {
        if (!pv[p]) continue;
        bool on = msk[b * HW + pi[p]] != 0;
#pragma unroll
        for (int j = 0; j < CONV_COT; j++)
            out[(long long)(b * Co + cobase + j) * HW + pi[p]] = on ? acc[p][j] : 0.0f;
    }
}

// ---------------------------------------------------------------------------
// 2x2 stride-2 masked max pool, CHW.
// ---------------------------------------------------------------------------
__global__ void k_pool_chw(const float* __restrict__ in, const unsigned char* __restrict__ mi,
                           float* __restrict__ out, int B, int C, int Ho, int Wo) {
    long long n = (long long)B * C * Ho * Wo;
    long long i = (long long)blockIdx.x * blockDim.x + threadIdx.x;
    if (i >= n) return;
    int xo = (int)(i % Wo); long long t = i / Wo;
    int yo = (int)(t % Ho); t /= Ho;
    int c = (int)(t % C);
    int b = (int)(t / C);
    int Wi = Wo * 2, Hi = Ho * 2;
    const unsigned char* mp = mi + ((long long)(b * Hi + 2 * yo) * Wi + 2 * xo);
    const float* ip = in + ((long long)((b * C + c) * Hi + 2 * yo) * Wi + 2 * xo);
    float best = -3.4e38f; int any = 0;
    if (mp[0])      { best = fmaxf(best, ip[0]);      any = 1; }
    if (mp[1])      { best = fmaxf(best, ip[1]);      any = 1; }
    if (mp[Wi])     { best = fmaxf(best, ip[Wi]);     any = 1; }
    if (mp[Wi + 1]) { best = fmaxf(best, ip[Wi + 1]); any = 1; }
    out[i] = any ? best : 0.0f;
}

__global__ void k_maskpool(const unsigned char* __restrict__ mi, unsigned char* __restrict__ mo,
                           int B, int Ho, int Wo) {
    int i = blockIdx.x * blockDim.x + threadIdx.x;
    int n = B * Ho * Wo;
    if (i >= n) return;
    int xo = i % Wo; int t = i / Wo;
    int yo = t % Ho; int b = t / Ho;
    int Wi = 2 * Wo;
    const unsigned char* p = mi + ((b * 2 * Ho + 2 * yo) * Wi + 2 * xo);
    mo[i] = (p[0] | p[1] | p[Wi] | p[Wi + 1]) ? 1 : 0;
}

__global__ void k_mc(const unsigned char* __restrict__ mcoarse,
                     const unsigned char* __restrict__ mfine,
                     unsigned char* __restrict__ mc, int B, int H, int W) {
    int i = blockIdx.x * blockDim.x + threadIdx.x;
    int n = B * H * W;
    if (i >= n) return;
    int x = i % W; int t = i / W;
    int y = t % H; int b = t / H;
    unsigned char v = mfine[i] | mcoarse[(b * (H / 2) + (y >> 1)) * (W / 2) + (x >> 1)];
    mc[i] = v ? 1 : 0;
}

// ---------------------------------------------------------------------------
// kernel-2 stride-2 transpose conv, CHW. Thread: 2 input pixels x T_COT co,
// produces the 2x2 output block of each. Weights [2,2,Ci,Co].
// ---------------------------------------------------------------------------
__global__ void tconv_chw(const float* __restrict__ in, const float* __restrict__ w,
                          float* __restrict__ out, int Hi, int Wi, int Ci, int Co) {
    const int HWi = Hi * Wi;
    const int HWo = HWi * 4;
    const int Wo = Wi * 2;
    const int b = blockIdx.z;
    const int cobase = blockIdx.y * T_COT;
    int p0 = blockIdx.x * 512 + threadIdx.x;
    int p1 = p0 + 256;
    bool v0 = p0 < HWi, v1 = p1 < HWi;
    const long long ds = (long long)Ci * Co;

    float acc[2][4][T_COT];
#pragma unroll
    for (int q = 0; q < 2; q++)
#pragma unroll
        for (int dt = 0; dt < 4; dt++)
#pragma unroll
            for (int j = 0; j < T_COT; j++) acc[q][dt][j] = 0.0f;

    for (int ci = 0; ci < Ci; ci++) {
        const float* wp = w + (long long)ci * Co + cobase;
        float4 wv[4];
#pragma unroll
        for (int dt = 0; dt < 4; dt++)
            wv[dt] = *reinterpret_cast<const float4*>(wp + dt * ds);
        const float* ip = in + (long long)(b * Ci + ci) * HWi;
        float x0 = v0 ? __ldg(ip + p0) : 0.0f;
        float x1 = v1 ? __ldg(ip + p1) : 0.0f;
#pragma unroll
        for (int dt = 0; dt < 4; dt++) {
            acc[0][dt][0] = fmaf(x0, wv[dt].x, acc[0][dt][0]);
            acc[0][dt][1] = fmaf(x0, wv[dt].y, acc[0][dt][1]);
            acc[0][dt][2] = fmaf(x0, wv[dt].z, acc[0][dt][2]);
            acc[0][dt][3] = fmaf(x0, wv[dt].w, acc[0][dt][3]);
            acc[1][dt][0] = fmaf(x1, wv[dt].x, acc[1][dt][0]);
            acc[1][dt][1] = fmaf(x1, wv[dt].y, acc[1][dt][1]);
            acc[1][dt][2] = fmaf(x1, wv[dt].z, acc[1][dt][2]);
            acc[1][dt][3] = fmaf(x1, wv[dt].w, acc[1][dt][3]);
        }
    }

    int ps[2] = {p0, p1};
    bool vs[2] = {v0, v1};
#pragma unroll
    for (int q = 0; q < 2; q++) {
        if (!vs[q]) continue;
        int y = ps[q] / Wi, x = ps[q] % Wi;
        long long obase = (long long)(b * Co + cobase) * HWo;
#pragma unroll
        for (int dt = 0; dt < 4; dt++) {
            int yo = 2 * y + (dt >> 1);
            int xo = 2 * x + (dt & 1);
            long long oo = obase + (long long)yo * Wo + xo;
#pragma unroll
            for (int j = 0; j < T_COT; j++)
                out[oo + (long long)j * HWo] = acc[q][dt][j];
        }
    }
}

// final 1x1 conv 16->3, CHW in, NHWC out
__global__ void k_out1x1_chw(const float* __restrict__ in, const float* __restrict__ w,
                             const unsigned char* __restrict__ msk,
                             float* __restrict__ out, int HW) {
    int n = NB * HW;
    int i = blockIdx.x * blockDim.x + threadIdx.x;
    if (i >= n) return;
    long long o = (long long)i * 3;
    if (!msk[i]) { out[o] = 0.0f; out[o + 1] = 0.0f; out[o + 2] = 0.0f; return; }
    int b = i / HW, pix = i % HW;
    float a0 = 0.0f, a1 = 0.0f, a2 = 0.0f;
#pragma unroll
    for (int c = 0; c < 16; c++) {
        float v = __ldg(in + (long long)(b * 16 + c) * HW + pix);
        a0 = fmaf(v, w[c * 3 + 0], a0);
        a1 = fmaf(v, w[c * 3 + 1], a1);
        a2 = fmaf(v, w[c * 3 + 2], a2);
    }
    out[o] = a0; out[o + 1] = a1; out[o + 2] = a2;
}

// CHW [B,32,HW] -> NHWC [B,HW,32] for the c2 output, smem-tiled
__global__ void k_tr_c2(const float* __restrict__ in, float* __restrict__ outp, int HW) {
    __shared__ float t[32][33];
    int b = blockIdx.y;
    int px0 = blockIdx.x * 32;
    int tx = threadIdx.x, ty = threadIdx.y;
#pragma unroll
    for (int k = 0; k < 4; k++) {
        int c = ty + k * 8;
        t[c][tx] = in[(long long)(b * 32 + c) * HW + px0 + tx];
    }
    __syncthreads();
#pragma unroll
    for (int k = 0; k < 4; k++) {
        int pl = ty + k * 8;
        outp[((long long)b * HW + px0 + pl) * 32 + tx] = t[tx][pl];
    }
}

// ---------------------------------------------------------------------------
static inline unsigned grid_for(long long n) { return (unsigned)((n + 255) / 256); }

extern "C" void kernel_launch(void* const* d_in, const int* in_sizes, int n_in,
                              void* d_out, int out_size) {
    (void)in_sizes; (void)n_in; (void)out_size;

    const float* x      = (const float*)d_in[0];
    const int*   mask   = (const int*)d_in[1];
    const float* w_ds1  = (const float*)d_in[2];
    const float* w_ds2  = (const float*)d_in[3];
    const float* w_ds3  = (const float*)d_in[4];
    const float* w_ds4  = (const float*)d_in[5];
    const float* w_brdg = (const float*)d_in[6];
    const float* wt4    = (const float*)d_in[7];
    const float* w_us4  = (const float*)d_in[8];
    const float* wt3    = (const float*)d_in[9];
    const float* w_us3  = (const float*)d_in[10];
    const float* wt2    = (const float*)d_in[11];
    const float* w_us2  = (const float*)d_in[12];
    const float* wt1    = (const float*)d_in[13];
    const float* w_us1  = (const float*)d_in[14];
    const float* w_out  = (const float*)d_in[15];

    float* out_final = (float*)d_out;                                    // [2,1024,1024,3]
    float* c2_out    = (float*)d_out + (long long)NB * 1024 * 1024 * 3;  // [2,512,512,32]

    float *xm, *c1, *p1, *c2, *p2, *c3, *p3, *c4, *p4, *br, *u4, *r4, *u3, *r3, *u2, *r2, *u1, *r1;
    unsigned char *m0, *m1, *m2, *m3, *m4, *mc4, *mc3, *mc2, *mc1;
    cudaGetSymbolAddress((void**)&xm, g_xm);
    cudaGetSymbolAddress((void**)&c1, g_c1);
    cudaGetSymbolAddress((void**)&p1, g_p1);
    cudaGetSymbolAddress((void**)&c2, g_c2);
    cudaGetSymbolAddress((void**)&p2, g_p2);
    cudaGetSymbolAddress((void**)&c3, g_c3);
    cudaGetSymbolAddress((void**)&p3, g_p3);
    cudaGetSymbolAddress((void**)&c4, g_c4);
    cudaGetSymbolAddress((void**)&p4, g_p4);
    cudaGetSymbolAddress((void**)&br, g_br);
    cudaGetSymbolAddress((void**)&u4, g_u4);
    cudaGetSymbolAddress((void**)&r4, g_r4);
    cudaGetSymbolAddress((void**)&u3, g_u3);
    cudaGetSymbolAddress((void**)&r3, g_r3);
    cudaGetSymbolAddress((void**)&u2, g_u2);
    cudaGetSymbolAddress((void**)&r2, g_r2);
    cudaGetSymbolAddress((void**)&u1, g_u1);
    cudaGetSymbolAddress((void**)&r1, g_r1);
    cudaGetSymbolAddress((void**)&m0, g_m0);
    cudaGetSymbolAddress((void**)&m1, g_m1);
    cudaGetSymbolAddress((void**)&m2, g_m2);
    cudaGetSymbolAddress((void**)&m3, g_m3);
    cudaGetSymbolAddress((void**)&m4, g_m4);
    cudaGetSymbolAddress((void**)&mc4, g_mc4);
    cudaGetSymbolAddress((void**)&mc3, g_mc3);
    cudaGetSymbolAddress((void**)&mc2, g_mc2);
    cudaGetSymbolAddress((void**)&mc1, g_mc1);

    const int TB = 256;
    long long n;

    n = (long long)NB * 1024 * 1024;
    k_init<<<grid_for(n), TB>>>(x, mask, xm, m0, (int)n);

    // --- encoder ---
    conv3_chw<<<dim3(1024, 16 / CONV_COT, NB), TB>>>(xm, nullptr, 1, 0, w_ds1, m0, c1, 1024, 1024, 16);

    n = (long long)NB * 512 * 512;
    k_maskpool<<<grid_for(n), TB>>>(m0, m1, NB, 512, 512);
    n = (long long)NB * 16 * 512 * 512;
    k_pool_chw<<<grid_for(n), TB>>>(c1, m0, p1, NB, 16, 512, 512);

    conv3_chw<<<dim3(256, 32 / CONV_COT, NB), TB>>>(p1, nullptr, 16, 0, w_ds2, m1, c2, 512, 512, 32);

    n = (long long)NB * 256 * 256;
    k_maskpool<<<grid_for(n), TB>>>(m1, m2, NB, 256, 256);
    n = (long long)NB * 32 * 256 * 256;
    k_pool_chw<<<grid_for(n), TB>>>(c2, m1, p2, NB, 32, 256, 256);

    conv3_chw<<<dim3(64, 64 / CONV_COT, NB), TB>>>(p2, nullptr, 32, 0, w_ds3, m2, c3, 256, 256, 64);

    n = (long long)NB * 128 * 128;
    k_maskpool<<<grid_for(n), TB>>>(m2, m3, NB, 128, 128);
    n = (long long)NB * 64 * 128 * 128;
    k_pool_chw<<<grid_for(n), TB>>>(c3, m2, p3, NB, 64, 128, 128);

    conv3_chw<<<dim3(16, 128 / CONV_COT, NB), TB>>>(p3, nullptr, 64, 0, w_ds4, m3, c4, 128, 128, 128);

    n = (long long)NB * 64 * 64;
    k_maskpool<<<grid_for(n), TB>>>(m3, m4, NB, 64, 64);
    n = (long long)NB * 128 * 64 * 64;
    k_pool_chw<<<grid_for(n), TB>>>(c4, m3, p4, NB, 128, 64, 64);

    // --- bridge ---
    conv3_chw<<<dim3(4, 256 / CONV_COT, NB), TB>>>(p4, nullptr, 128, 0, w_brdg, m4, br, 64, 64, 256);

    // --- decoder 4 ---
    tconv_chw<<<dim3(8, 128 / T_COT, NB), TB>>>(br, wt4, u4, 64, 64, 256, 128);
    n = (long long)NB * 128 * 128;
    k_mc<<<grid_for(n), TB>>>(m4, m3, mc4, NB, 128, 128);
    conv3_chw<<<dim3(16, 128 / CONV_COT, NB), TB>>>(u4, c4, 128, 128, w_us4, mc4, r4, 128, 128, 128);

    // --- decoder 3 ---
    tconv_chw<<<dim3(32, 64 / T_COT, NB), TB>>>(r4, wt3, u3, 128, 128, 128, 64);
    n = (long long)NB * 256 * 256;
    k_mc<<<grid_for(n), TB>>>(mc4, m2, mc3, NB, 256, 256);
    conv3_chw<<<dim3(64, 64 / CONV_COT, NB), TB>>>(u3, c3, 64, 64, w_us3, mc3, r3, 256, 256, 64);

    // --- decoder 2 ---
    tconv_chw<<<dim3(128, 32 / T_COT, NB), TB>>>(r3, wt2, u2, 256, 256, 64, 32);
    n = (long long)NB * 512 * 512;
    k_mc<<<grid_for(n), TB>>>(mc3, m1, mc2, NB, 512, 512);
    conv3_chw<<<dim3(256, 32 / CONV_COT, NB), TB>>>(u2, c2, 32, 32, w_us2, mc2, r2, 512, 512, 32);

    // --- decoder 1 ---
    tconv_chw<<<dim3(512, 16 / T_COT, NB), TB>>>(r2, wt1, u1, 512, 512, 32, 16);
    n = (long long)NB * 1024 * 1024;
    k_mc<<<grid_for(n), TB>>>(mc2, m0, mc1, NB, 1024, 1024);
    conv3_chw<<<dim3(1024, 16 / CONV_COT, NB), TB>>>(u1, c1, 16, 16, w_us1, mc1, r1, 1024, 1024, 16);

    // --- outputs ---
    n = (long long)NB * 1024 * 1024;
    k_out1x1_chw<<<grid_for(n), TB>>>(r1, w_out, mc1, out_final, 1024 * 1024);

    k_tr_c2<<<dim3(512 * 512 / 32, NB), dim3(32, 8)>>>(c2, c2_out, 512 * 512);
}